// round 1
// baseline (speedup 1.0000x reference)
#include <cuda_runtime.h>
#include <math.h>

// Problem constants
#define BATCH 16
#define DIMC  512
#define NPTS  4096

// Scratch (device globals are the only legal scratch)
__device__ float g_G[BATCH * DIMC * DIMC];  // x x^T per batch
__device__ float g_T[BATCH * DIMC * DIMC];  // Wq @ G
__device__ float g_S[BATCH * DIMC * DIMC];  // logits / attn (in-place softmax)
__device__ float g_M[BATCH * DIMC * DIMC];  // attn @ Wv

// ---------------------------------------------------------------------------
// Generic batched SGEMM:  C = alpha * A * op(B)
//   A: [M,K] row-major, lda
//   op(B): if !TB, B is [K,N] row-major (ldb = N-stride); if TB, B stored [N,K]
//          and we use B^T (dot rows of B), ldb = K-stride.
// Tiles: 128x128x16, 256 threads, 8x8 per thread.
// All dims here divide the tile sizes exactly; no bounds checks.
// ---------------------------------------------------------------------------
template <bool TB>
__global__ __launch_bounds__(256) void sgemm_kernel(
    const float* __restrict__ A, const float* __restrict__ B, float* __restrict__ C,
    int M, int Nn, int K, int lda, int ldb, int ldc,
    long long strideA, long long strideB, long long strideC, float alpha)
{
    constexpr int BM = 128, BN = 128, BK = 16;
    __shared__ float As[BK][BM];
    __shared__ float Bs[BK][BN];

    const int bz = blockIdx.z;
    A += bz * strideA;
    B += bz * strideB;
    C += bz * strideC;

    const int brow = blockIdx.y * BM;
    const int bcol = blockIdx.x * BN;
    const int tid  = threadIdx.x;
    const int tx   = tid & 15;   // 0..15 -> column group
    const int ty   = tid >> 4;   // 0..15 -> row group

    // A-tile loader mapping: 4 threads per row along k (float4), 64 rows/pass
    const int a_row0 = tid >> 2;        // 0..63
    const int a_col  = (tid & 3) * 4;   // 0,4,8,12
    // B-tile NN loader mapping: 32 threads per row along n (float4), 8 rows/pass
    const int b_row0 = tid >> 5;        // 0..7
    const int b_col  = (tid & 31) * 4;

    float acc[8][8];
#pragma unroll
    for (int i = 0; i < 8; i++)
#pragma unroll
        for (int j = 0; j < 8; j++) acc[i][j] = 0.0f;

    for (int k0 = 0; k0 < K; k0 += BK) {
        // ---- load A tile (BM x BK), stored transposed As[k][m]
#pragma unroll
        for (int p = 0; p < 2; ++p) {
            const int r = a_row0 + p * 64;
            float4 v = *(const float4*)(A + (long long)(brow + r) * lda + k0 + a_col);
            As[a_col + 0][r] = v.x;
            As[a_col + 1][r] = v.y;
            As[a_col + 2][r] = v.z;
            As[a_col + 3][r] = v.w;
        }
        // ---- load B tile into Bs[k][n]
        if (!TB) {
#pragma unroll
            for (int p = 0; p < 2; ++p) {
                const int r = b_row0 + p * 8;
                float4 v = *(const float4*)(B + (long long)(k0 + r) * ldb + bcol + b_col);
                *(float4*)&Bs[r][b_col] = v;
            }
        } else {
#pragma unroll
            for (int p = 0; p < 2; ++p) {
                const int r = a_row0 + p * 64;  // output-column index within tile
                float4 v = *(const float4*)(B + (long long)(bcol + r) * ldb + k0 + a_col);
                Bs[a_col + 0][r] = v.x;
                Bs[a_col + 1][r] = v.y;
                Bs[a_col + 2][r] = v.z;
                Bs[a_col + 3][r] = v.w;
            }
        }
        __syncthreads();

#pragma unroll
        for (int k = 0; k < BK; ++k) {
            float ra[8], rb[8];
#pragma unroll
            for (int i = 0; i < 8; i++) ra[i] = As[k][ty * 8 + i];
#pragma unroll
            for (int j = 0; j < 8; j++) rb[j] = Bs[k][tx * 8 + j];
#pragma unroll
            for (int i = 0; i < 8; i++)
#pragma unroll
                for (int j = 0; j < 8; j++) acc[i][j] += ra[i] * rb[j];
        }
        __syncthreads();
    }

    // ---- epilogue
#pragma unroll
    for (int i = 0; i < 8; i++) {
        const int r = brow + ty * 8 + i;
#pragma unroll
        for (int j = 0; j < 8; j += 4) {
            float4 v = make_float4(acc[i][j + 0] * alpha, acc[i][j + 1] * alpha,
                                   acc[i][j + 2] * alpha, acc[i][j + 3] * alpha);
            *(float4*)(C + (long long)r * ldc + bcol + tx * 8 + j) = v;
        }
    }
}

// ---------------------------------------------------------------------------
// Row softmax over S: [BATCH*DIMC rows, DIMC cols], in place.
// One block (256 threads) per row; each thread owns 2 columns.
// ---------------------------------------------------------------------------
__global__ __launch_bounds__(256) void softmax_kernel(float* __restrict__ S)
{
    __shared__ float red[256];
    const long long row = blockIdx.x;
    float* p = S + row * DIMC;
    const int t = threadIdx.x;

    float v0 = p[t];
    float v1 = p[t + 256];

    // max reduction
    red[t] = fmaxf(v0, v1);
    __syncthreads();
#pragma unroll
    for (int s = 128; s > 0; s >>= 1) {
        if (t < s) red[t] = fmaxf(red[t], red[t + s]);
        __syncthreads();
    }
    const float m = red[0];
    __syncthreads();

    const float e0 = expf(v0 - m);
    const float e1 = expf(v1 - m);

    // sum reduction
    red[t] = e0 + e1;
    __syncthreads();
#pragma unroll
    for (int s = 128; s > 0; s >>= 1) {
        if (t < s) red[t] += red[t + s];
        __syncthreads();
    }
    const float inv = 1.0f / red[0];

    p[t]       = e0 * inv;
    p[t + 256] = e1 * inv;
}

// ---------------------------------------------------------------------------
// Launch:
//   G = x x^T                (NT, K=4096)
//   T = Wq G                 (NN)
//   S = (1/tau) * T Wk^T     (NT)
//   A = softmax_rows(S)      (in place)
//   M = A Wv                 (NN)
//   out = M x                (NN, N=4096)
// ---------------------------------------------------------------------------
extern "C" void kernel_launch(void* const* d_in, const int* in_sizes, int n_in,
                              void* d_out, int out_size)
{
    const float* x  = (const float*)d_in[0];
    const float* Wq = (const float*)d_in[1];
    const float* Wk = (const float*)d_in[2];
    const float* Wv = (const float*)d_in[3];
    float* out = (float*)d_out;

    float *G, *T, *S, *Mm;
    cudaGetSymbolAddress((void**)&G,  g_G);
    cudaGetSymbolAddress((void**)&T,  g_T);
    cudaGetSymbolAddress((void**)&S,  g_S);
    cudaGetSymbolAddress((void**)&Mm, g_M);

    const long long sXB = (long long)DIMC * NPTS;   // per-batch stride of x / out
    const long long sDD = (long long)DIMC * DIMC;   // per-batch stride of square mats
    const float inv_tau = (float)(1.0 / sqrt((double)DIMC));

    dim3 gSq(DIMC / 128, DIMC / 128, BATCH);   // 4 x 4 x 16
    dim3 gOut(NPTS / 128, DIMC / 128, BATCH);  // 32 x 4 x 16

    // G[b] = x[b] x[b]^T   (A = x[b] [512,4096]; B = x[b] rows dotted)
    sgemm_kernel<true><<<gSq, 256>>>(x, x, G,
        DIMC, DIMC, NPTS, NPTS, NPTS, DIMC,
        sXB, sXB, sDD, 1.0f);

    // T[b] = Wq @ G[b]
    sgemm_kernel<false><<<gSq, 256>>>(Wq, G, T,
        DIMC, DIMC, DIMC, DIMC, DIMC, DIMC,
        0LL, sDD, sDD, 1.0f);

    // S[b] = (1/tau) * T[b] @ Wk^T
    sgemm_kernel<true><<<gSq, 256>>>(T, Wk, S,
        DIMC, DIMC, DIMC, DIMC, DIMC, DIMC,
        sDD, 0LL, sDD, inv_tau);

    // softmax over rows of S
    softmax_kernel<<<BATCH * DIMC, 256>>>(S);

    // M[b] = A[b] @ Wv
    sgemm_kernel<false><<<gSq, 256>>>(S, Wv, Mm,
        DIMC, DIMC, DIMC, DIMC, DIMC, DIMC,
        sDD, 0LL, sDD, 1.0f);

    // out[b] = M[b] @ x[b]
    sgemm_kernel<false><<<gOut, 256>>>(Mm, x, out,
        DIMC, NPTS, DIMC, DIMC, NPTS, NPTS,
        sDD, sXB, sXB, 1.0f);
}

// round 5
// speedup vs baseline: 1.3105x; 1.3105x over previous
#include <cuda_runtime.h>
#include <cstdint>
#include <math.h>

// Problem constants
#define BATCH 16
#define DIMC  512
#define NPTS  4096

// Scratch (device globals — only legal scratch)
__device__ float g_G[BATCH * DIMC * DIMC];    // x x^T (symmetric)
__device__ float g_T[BATCH * DIMC * DIMC];    // Wq @ G
__device__ float g_S[BATCH * DIMC * DIMC];    // logits / attn (in-place softmax)
__device__ float g_M[BATCH * DIMC * DIMC];    // attn @ Wv
__device__ float g_xT[BATCH * DIMC * NPTS];   // x transposed per batch: [N, DIM]
__device__ float g_WvT[DIMC * DIMC];          // Wv^T

// ===========================================================================
// Helpers
// ===========================================================================
__device__ __forceinline__ uint32_t f2tf32(float x) {
    uint32_t r;
    asm("cvt.rna.tf32.f32 %0, %1;" : "=r"(r) : "f"(x));
    return r;
}

// Split float into tf32 hi + tf32 lo (covers ~21 mantissa bits)
__device__ __forceinline__ void tf32_split(float v, uint32_t& hi, uint32_t& lo) {
    hi = f2tf32(v);
    float r = v - __uint_as_float(hi);
    lo = f2tf32(r);
}

#define CP_ASYNC16(saddr, gptr) \
    asm volatile("cp.async.cg.shared.global [%0], [%1], 16;" \
        :: "r"(saddr), "l"(gptr) : "memory")
#define CP_COMMIT()  asm volatile("cp.async.commit_group;" ::: "memory")
#define CP_WAIT(n)   asm volatile("cp.async.wait_group %0;" :: "n"(n) : "memory")

__device__ __forceinline__ uint32_t smem_u32(const void* p) {
    uint32_t a;
    asm("{ .reg .u64 t; cvta.to.shared.u64 t, %1; cvt.u32.u64 %0, t; }"
        : "=r"(a) : "l"(p));
    return a;
}

__device__ __forceinline__ void mma_tf32(
    float c[4], uint32_t a0, uint32_t a1, uint32_t a2, uint32_t a3,
    uint32_t b0, uint32_t b1)
{
    asm volatile(
        "mma.sync.aligned.m16n8k8.row.col.f32.tf32.tf32.f32 "
        "{%0,%1,%2,%3}, {%4,%5,%6,%7}, {%8,%9}, {%0,%1,%2,%3};"
        : "+f"(c[0]), "+f"(c[1]), "+f"(c[2]), "+f"(c[3])
        : "r"(a0), "r"(a1), "r"(a2), "r"(a3), "r"(b0), "r"(b1));
}

// ===========================================================================
// 3xTF32 mma.sync NT GEMM:  C[m][n] = alpha * sum_k A[m][k] * B[n][k]
// Split-precision: acc += Alo*Bhi + Ahi*Blo + Ahi*Bhi  (error ~2^-22)
// A: [M,K] K-major (lda), B: [N,K] K-major (ldb), C: [M,N] row-major (ldc).
// CTA tile 128x128, BK=32. 8 warps: 2(m) x 4(n); warp tile 64x32.
// cp.async 2-stage pipeline. All dims divide tiles exactly.
// ===========================================================================
#define BM 128
#define BN 128
#define BKF 32
#define LDS_ROW 36                          // floats per smem row (pad: conflict-free)
#define TILE_FLOATS (128 * LDS_ROW)         // 4608 floats per operand tile
#define STAGE_FLOATS (2 * TILE_FLOATS)      // A + B
#define SMEM_FLOATS (2 * STAGE_FLOATS)      // 2 stages
#define SMEM_BYTES (SMEM_FLOATS * 4)        // 73728

__global__ __launch_bounds__(256) void gemm_tf32_nt(
    const float* __restrict__ A, const float* __restrict__ B, float* __restrict__ C,
    int K, int lda, int ldb, int ldc,
    long long strideA, long long strideB, long long strideC, float alpha)
{
    extern __shared__ float smem[];
    const int tid  = threadIdx.x;
    const int wid  = tid >> 5;
    const int lane = tid & 31;
    const int wm   = wid & 1;       // warp row (0..1)  -> 64 rows
    const int wn   = wid >> 1;      // warp col (0..3)  -> 32 cols

    A += blockIdx.z * strideA + (long long)(blockIdx.y * BM) * lda;
    B += blockIdx.z * strideB + (long long)(blockIdx.x * BN) * ldb;
    C += blockIdx.z * strideC;

    const uint32_t smem_base = smem_u32(smem);

    float acc[4][4][4];
#pragma unroll
    for (int i = 0; i < 4; i++)
#pragma unroll
        for (int j = 0; j < 4; j++)
#pragma unroll
            for (int r = 0; r < 4; r++) acc[i][j][r] = 0.0f;

    const int ktiles = K / BKF;

    // cp.async tile issue: 1024 16B-chunks per operand, 256 threads -> 4 each
    auto issue_tile = [&](int kt, int st) {
        const int kbase = kt * BKF;
        const uint32_t sA = smem_base + (uint32_t)(st * STAGE_FLOATS) * 4u;
        const uint32_t sB = sA + (uint32_t)TILE_FLOATS * 4u;
#pragma unroll
        for (int p = 0; p < 4; ++p) {
            const int c   = tid + p * 256;   // 0..1023
            const int row = c >> 3;
            const int q   = c & 7;
            const uint32_t soff = (uint32_t)(row * LDS_ROW + q * 4) * 4u;
            CP_ASYNC16(sA + soff, A + (long long)row * lda + kbase + q * 4);
            CP_ASYNC16(sB + soff, B + (long long)row * ldb + kbase + q * 4);
        }
        CP_COMMIT();
    };

    issue_tile(0, 0);
    if (ktiles > 1) issue_tile(1, 1);

    const int gid = lane >> 2;   // 0..7
    const int tig = lane & 3;    // 0..3

    for (int kt = 0; kt < ktiles; ++kt) {
        const int st = kt & 1;
        if (kt + 1 < ktiles) { CP_WAIT(1); } else { CP_WAIT(0); }
        __syncthreads();

        const float* As = smem + st * STAGE_FLOATS;
        const float* Bs = As + TILE_FLOATS;

#pragma unroll
        for (int s = 0; s < 4; ++s) {           // 4 x k8 steps
            const int kk = s * 8 + tig;
            uint32_t ah[4][4], al[4][4];
#pragma unroll
            for (int fi = 0; fi < 4; ++fi) {
                const int r = wm * 64 + fi * 16 + gid;
                const float* p = As + r * LDS_ROW + kk;
                tf32_split(p[0],                ah[fi][0], al[fi][0]);
                tf32_split(p[8 * LDS_ROW],      ah[fi][1], al[fi][1]);
                tf32_split(p[4],                ah[fi][2], al[fi][2]);
                tf32_split(p[8 * LDS_ROW + 4],  ah[fi][3], al[fi][3]);
            }
            uint32_t bh[4][2], bl[4][2];
#pragma unroll
            for (int fj = 0; fj < 4; ++fj) {
                const int n = wn * 32 + fj * 8 + gid;
                const float* p = Bs + n * LDS_ROW + kk;
                tf32_split(p[0], bh[fj][0], bl[fj][0]);
                tf32_split(p[4], bh[fj][1], bl[fj][1]);
            }
#pragma unroll
            for (int fi = 0; fi < 4; ++fi)
#pragma unroll
                for (int fj = 0; fj < 4; ++fj) {
                    // cross terms first, then main (slightly better numerics)
                    mma_tf32(acc[fi][fj], al[fi][0], al[fi][1], al[fi][2], al[fi][3],
                             bh[fj][0], bh[fj][1]);
                    mma_tf32(acc[fi][fj], ah[fi][0], ah[fi][1], ah[fi][2], ah[fi][3],
                             bl[fj][0], bl[fj][1]);
                    mma_tf32(acc[fi][fj], ah[fi][0], ah[fi][1], ah[fi][2], ah[fi][3],
                             bh[fj][0], bh[fj][1]);
                }
        }
        __syncthreads();
        if (kt + 2 < ktiles) issue_tile(kt + 2, st);
    }

    // Epilogue: c0/c1 at (row, 2*tig..+1), c2/c3 at (row+8, ...)
    const int crow0 = blockIdx.y * BM + wm * 64 + gid;
    const int ccol0 = blockIdx.x * BN + wn * 32 + 2 * tig;
#pragma unroll
    for (int fi = 0; fi < 4; ++fi) {
#pragma unroll
        for (int fj = 0; fj < 4; ++fj) {
            float* p0 = C + (long long)(crow0 + fi * 16) * ldc + ccol0 + fj * 8;
            float* p1 = p0 + 8 * ldc;
            *(float2*)p0 = make_float2(acc[fi][fj][0] * alpha, acc[fi][fj][1] * alpha);
            *(float2*)p1 = make_float2(acc[fi][fj][2] * alpha, acc[fi][fj][3] * alpha);
        }
    }
}

// ===========================================================================
// Tiled transpose: out[c][r] = in[r][c], per batch (blockIdx.z).
// ===========================================================================
__global__ __launch_bounds__(256) void transpose_kernel(
    const float* __restrict__ in, float* __restrict__ out,
    int rows, int cols, long long sin, long long sout)
{
    __shared__ float t[32][33];
    const float* I = in  + (long long)blockIdx.z * sin;
    float*       O = out + (long long)blockIdx.z * sout;
    const int c0 = blockIdx.x * 32;
    const int r0 = blockIdx.y * 32;
    const int tx = threadIdx.x, ty = threadIdx.y;
#pragma unroll
    for (int i = ty; i < 32; i += 8)
        t[i][tx] = I[(long long)(r0 + i) * cols + c0 + tx];
    __syncthreads();
#pragma unroll
    for (int i = ty; i < 32; i += 8)
        O[(long long)(c0 + i) * rows + r0 + tx] = t[tx][i];
}

// ===========================================================================
// Row softmax over S: [BATCH*DIMC rows, DIMC cols], in place. shfl reductions.
// ===========================================================================
__global__ __launch_bounds__(256) void softmax_kernel(float* __restrict__ S)
{
    __shared__ float red[8];
    const long long row = blockIdx.x;
    float* p = S + row * DIMC;
    const int t = threadIdx.x;
    const int lane = t & 31, warp = t >> 5;

    float v0 = p[t];
    float v1 = p[t + 256];

    float m = fmaxf(v0, v1);
#pragma unroll
    for (int o = 16; o; o >>= 1) m = fmaxf(m, __shfl_xor_sync(0xFFFFFFFFu, m, o));
    if (lane == 0) red[warp] = m;
    __syncthreads();
    m = red[0];
#pragma unroll
    for (int w = 1; w < 8; ++w) m = fmaxf(m, red[w]);
    __syncthreads();

    const float e0 = expf(v0 - m);
    const float e1 = expf(v1 - m);
    float sum = e0 + e1;
#pragma unroll
    for (int o = 16; o; o >>= 1) sum += __shfl_xor_sync(0xFFFFFFFFu, sum, o);
    if (lane == 0) red[warp] = sum;
    __syncthreads();
    sum = red[0];
#pragma unroll
    for (int w = 1; w < 8; ++w) sum += red[w];
    const float inv = 1.0f / sum;

    p[t]       = e0 * inv;
    p[t + 256] = e1 * inv;
}

// ===========================================================================
// Launch chain (all GEMMs native NT, 3xTF32 mma.sync):
//   xT = transpose(x); WvT = transpose(Wv)
//   G = x.x^T (K=4096); T = Wq.G (G symmetric); S = (1/tau) T.Wk^T
//   A = softmax(S); M = A.Wv (via WvT); out = M.x (via xT)
// ===========================================================================
extern "C" void kernel_launch(void* const* d_in, const int* in_sizes, int n_in,
                              void* d_out, int out_size)
{
    const float* x  = (const float*)d_in[0];
    const float* Wq = (const float*)d_in[1];
    const float* Wk = (const float*)d_in[2];
    const float* Wv = (const float*)d_in[3];
    float* out = (float*)d_out;

    float *G, *T, *S, *Mm, *xT, *WvT;
    cudaGetSymbolAddress((void**)&G,   g_G);
    cudaGetSymbolAddress((void**)&T,   g_T);
    cudaGetSymbolAddress((void**)&S,   g_S);
    cudaGetSymbolAddress((void**)&Mm,  g_M);
    cudaGetSymbolAddress((void**)&xT,  g_xT);
    cudaGetSymbolAddress((void**)&WvT, g_WvT);

    cudaFuncSetAttribute(gemm_tf32_nt,
                         cudaFuncAttributeMaxDynamicSharedMemorySize, SMEM_BYTES);

    const long long sXB = (long long)DIMC * NPTS;
    const long long sDD = (long long)DIMC * DIMC;
    const float inv_tau = (float)(1.0 / sqrt((double)DIMC));

    {
        dim3 g(NPTS / 32, DIMC / 32, BATCH);
        transpose_kernel<<<g, dim3(32, 8)>>>(x, xT, DIMC, NPTS, sXB, sXB);
        dim3 gw(DIMC / 32, DIMC / 32, 1);
        transpose_kernel<<<gw, dim3(32, 8)>>>(Wv, WvT, DIMC, DIMC, 0LL, 0LL);
    }

    dim3 gSq(DIMC / BN, DIMC / BM, BATCH);   // 4 x 4 x 16
    dim3 gOut(NPTS / BN, DIMC / BM, BATCH);  // 32 x 4 x 16

    // G[b] = x[b] . x[b]^T
    gemm_tf32_nt<<<gSq, 256, SMEM_BYTES>>>(x, x, G,
        NPTS, NPTS, NPTS, DIMC, sXB, sXB, sDD, 1.0f);

    // T[b] = Wq . G[b]   (G symmetric)
    gemm_tf32_nt<<<gSq, 256, SMEM_BYTES>>>(Wq, G, T,
        DIMC, DIMC, DIMC, DIMC, 0LL, sDD, sDD, 1.0f);

    // S[b] = (1/tau) T[b] . Wk^T
    gemm_tf32_nt<<<gSq, 256, SMEM_BYTES>>>(T, Wk, S,
        DIMC, DIMC, DIMC, DIMC, sDD, 0LL, sDD, inv_tau);

    softmax_kernel<<<BATCH * DIMC, 256>>>(S);

    // M[b] = A[b] . Wv   (B = WvT)
    gemm_tf32_nt<<<gSq, 256, SMEM_BYTES>>>(S, WvT, Mm,
        DIMC, DIMC, DIMC, DIMC, sDD, 0LL, sDD, 1.0f);

    // out[b] = M[b] . x[b]  (B = xT)
    gemm_tf32_nt<<<gOut, 256, SMEM_BYTES>>>(Mm, xT, out,
        DIMC, DIMC, DIMC, NPTS, sDD, sXB, sXB, 1.0f);
}